// round 4
// baseline (speedup 1.0000x reference)
#include <cuda_runtime.h>
#include <math.h>

// Fused kernel: warp 0 of every block recomputes the tiny batch-independent
// prep {M1, M2, alpha, beta, c} into shared memory (weights are L2-resident),
// while all threads' x-loads are already in flight. Then each thread applies
//   out_b = alpha * cross(M1 x_b, M2 x_b) + beta * x_b + c
// to 8 states (6 float4 loads + 6 float4 stores).

__global__ void fused_kernel(const float* __restrict__ t,
                             const float* __restrict__ x,
                             const float* __restrict__ R,
                             const float* __restrict__ m,
                             const float* __restrict__ Wl1, const float* __restrict__ Wd1,
                             const float* __restrict__ Wl2, const float* __restrict__ Wd2,
                             const float* __restrict__ Wl3, const float* __restrict__ Wd3,
                             const float* __restrict__ Wl4, const float* __restrict__ Wd4,
                             const float* __restrict__ Wb1_lin,
                             const float* __restrict__ Wb1_d1, const float* __restrict__ Wb1_d2,
                             const float* __restrict__ Wb2_lin,
                             const float* __restrict__ Wb2_d1, const float* __restrict__ Wb2_d2,
                             const float* __restrict__ Wout,
                             float* __restrict__ out,
                             int nOct, int nstates)
{
    __shared__ float mm[20][3];     // mm[f][k] = (R@m)[k][f]
    __shared__ float sM[4][9];      // M1..M4
    __shared__ float s_prep[23];    // [0..8] M1, [9..17] M2, [18] a, [19] b, [20..22] c

    const int tid = blockIdx.x * blockDim.x + threadIdx.x;
    const int lane = threadIdx.x;

    // ---- Front-batch the x loads (independent of prep; latency hides behind it)
    const float4* __restrict__ x4 = (const float4*)x;
    float4* __restrict__ o4 = (float4*)out;
    const bool active = tid < nOct;
    const long base = (long)tid * 6;
    float4 v0, v1, v2, v3, v4, v5;
    if (active) {
        v0 = x4[base + 0]; v1 = x4[base + 1]; v2 = x4[base + 2];
        v3 = x4[base + 3]; v4 = x4[base + 4]; v5 = x4[base + 5];
    }

    // ---- Per-block redundant prep (warp 0 only)
    if (lane < 32) {
        // mm = (R @ m)^T
        for (int idx = lane; idx < 60; idx += 32) {
            int f = idx / 3, k = idx % 3;
            float s = 0.f;
            #pragma unroll
            for (int j = 0; j < 3; ++j) s += R[k * 3 + j] * m[j * 20 + f];
            mm[f][k] = s;
        }
        __syncwarp();

        if (lane < 4) {
            const float* Wl = (lane == 0) ? Wl1 : (lane == 1) ? Wl2 : (lane == 2) ? Wl3 : Wl4;
            const float* Wd = (lane == 0) ? Wd1 : (lane == 1) ? Wd2 : (lane == 2) ? Wd3 : Wd4;
            float y[3][3], d[3][3], o[3][3];
            #pragma unroll
            for (int oo = 0; oo < 3; ++oo)
                #pragma unroll
                for (int k = 0; k < 3; ++k) {
                    float s = 0.f;
                    #pragma unroll
                    for (int f = 0; f < 20; ++f) s += Wl[oo * 20 + f] * mm[f][k];
                    y[oo][k] = s;
                }
            #pragma unroll
            for (int oo = 0; oo < 3; ++oo)
                #pragma unroll
                for (int k = 0; k < 3; ++k) {
                    float s = 0.f;
                    #pragma unroll
                    for (int f = 0; f < 3; ++f) s += Wd[oo * 3 + f] * y[f][k];
                    d[oo][k] = s;
                }
            #pragma unroll
            for (int oo = 0; oo < 3; ++oo) {
                float kxd = -2.f * (y[oo][0] * d[oo][0] + y[oo][1] * d[oo][1] + y[oo][2] * d[oo][2]);
                float kdd = -2.f * (d[oo][0] * d[oo][0] + d[oo][1] * d[oo][1] + d[oo][2] * d[oo][2]);
                float denom = fminf(kdd, -1e-12f);
                float fac = (kxd < 0.f) ? 0.f : (kxd / denom);
                #pragma unroll
                for (int k = 0; k < 3; ++k) o[oo][k] = y[oo][k] - fac * d[oo][k];
            }
            #pragma unroll
            for (int p = 0; p < 3; ++p)
                #pragma unroll
                for (int q = 0; q < 3; ++q)
                    sM[lane][p * 3 + q] =
                        o[0][p] * o[0][q] + o[1][p] * o[1][q] + o[2][p] * o[2][q];
        }
        __syncwarp();

        // Per-channel contractions
        float pa = 0.f, pb = 0.f, pau = 0.f, pbu = 0.f;
        if (lane < 20) {
            float c1 = 0.f, c2 = 0.f, c1u = 0.f, c2u = 0.f;
            #pragma unroll 4
            for (int q = 0; q < 20; ++q) {
                float b1 = Wb1_lin[q], b2 = Wb2_lin[q];
                c1  += Wb1_d1[lane * 20 + q] * b1;
                c2  += Wb1_d2[lane * 20 + q] * b1;
                c1u += Wb2_d1[lane * 20 + q] * b2;
                c2u += Wb2_d2[lane * 20 + q] * b2;
            }
            float wo = Wout[lane];
            pa  = wo * c1 * c2;
            pb  = wo * Wb1_lin[lane];
            pau = wo * c1u * c2u;
            pbu = wo * Wb2_lin[lane];
        }
        #pragma unroll
        for (int off = 16; off; off >>= 1) {
            pa  += __shfl_down_sync(0xffffffffu, pa, off);
            pb  += __shfl_down_sync(0xffffffffu, pb, off);
            pau += __shfl_down_sync(0xffffffffu, pau, off);
            pbu += __shfl_down_sync(0xffffffffu, pbu, off);
        }

        if (lane == 0) {
            float tv = t[0];
            float sv = sinf(tv), cv = cosf(tv);
            float u0[3] = {10.f * sv, 10.f * cv, 10.f * sv};
            float u[3];
            #pragma unroll
            for (int k = 0; k < 3; ++k)
                u[k] = R[k * 3 + 0] * u0[0] + R[k * 3 + 1] * u0[1] + R[k * 3 + 2] * u0[2];
            float w1[3], w2[3];
            #pragma unroll
            for (int p = 0; p < 3; ++p) {
                w1[p] = sM[2][p * 3 + 0] * u[0] + sM[2][p * 3 + 1] * u[1] + sM[2][p * 3 + 2] * u[2];
                w2[p] = sM[3][p * 3 + 0] * u[0] + sM[3][p * 3 + 1] * u[1] + sM[3][p * 3 + 2] * u[2];
            }
            float cu[3] = {w1[1] * w2[2] - w1[2] * w2[1],
                           w1[2] * w2[0] - w1[0] * w2[2],
                           w1[0] * w2[1] - w1[1] * w2[0]};
            #pragma unroll
            for (int i = 0; i < 9; ++i) { s_prep[i] = sM[0][i]; s_prep[9 + i] = sM[1][i]; }
            s_prep[18] = pa;
            s_prep[19] = pb;
            #pragma unroll
            for (int k = 0; k < 3; ++k) s_prep[20 + k] = pau * cu[k] + pbu * u[k];
        }
    }
    __syncthreads();

    float M1[9], M2[9];
    #pragma unroll
    for (int j = 0; j < 9; ++j) { M1[j] = s_prep[j]; M2[j] = s_prep[9 + j]; }
    const float al = s_prep[18], be = s_prep[19];
    const float c0 = s_prep[20], c1 = s_prep[21], c2 = s_prep[22];

    if (active) {
        float xs[24] = {v0.x, v0.y, v0.z, v0.w, v1.x, v1.y, v1.z, v1.w,
                        v2.x, v2.y, v2.z, v2.w, v3.x, v3.y, v3.z, v3.w,
                        v4.x, v4.y, v4.z, v4.w, v5.x, v5.y, v5.z, v5.w};
        float os[24];
        #pragma unroll
        for (int s = 0; s < 8; ++s) {
            float px = xs[3 * s + 0], py = xs[3 * s + 1], pz = xs[3 * s + 2];
            float y0 = M1[0] * px + M1[1] * py + M1[2] * pz;
            float y1 = M1[3] * px + M1[4] * py + M1[5] * pz;
            float y2 = M1[6] * px + M1[7] * py + M1[8] * pz;
            float z0 = M2[0] * px + M2[1] * py + M2[2] * pz;
            float z1 = M2[3] * px + M2[4] * py + M2[5] * pz;
            float z2 = M2[6] * px + M2[7] * py + M2[8] * pz;
            os[3 * s + 0] = al * (y1 * z2 - y2 * z1) + be * px + c0;
            os[3 * s + 1] = al * (y2 * z0 - y0 * z2) + be * py + c1;
            os[3 * s + 2] = al * (y0 * z1 - y1 * z0) + be * pz + c2;
        }
        o4[base + 0] = make_float4(os[0],  os[1],  os[2],  os[3]);
        o4[base + 1] = make_float4(os[4],  os[5],  os[6],  os[7]);
        o4[base + 2] = make_float4(os[8],  os[9],  os[10], os[11]);
        o4[base + 3] = make_float4(os[12], os[13], os[14], os[15]);
        o4[base + 4] = make_float4(os[16], os[17], os[18], os[19]);
        o4[base + 5] = make_float4(os[20], os[21], os[22], os[23]);
    }

    // Scalar tail (nstates % 8 != 0) — handled by one thread; empty for B=1e6.
    if (tid == 0) {
        for (int s = nOct * 8; s < nstates; ++s) {
            float px = x[3 * s], py = x[3 * s + 1], pz = x[3 * s + 2];
            float y0 = M1[0] * px + M1[1] * py + M1[2] * pz;
            float y1 = M1[3] * px + M1[4] * py + M1[5] * pz;
            float y2 = M1[6] * px + M1[7] * py + M1[8] * pz;
            float z0 = M2[0] * px + M2[1] * py + M2[2] * pz;
            float z1 = M2[3] * px + M2[4] * py + M2[5] * pz;
            float z2 = M2[6] * px + M2[7] * py + M2[8] * pz;
            out[3 * s + 0] = al * (y1 * z2 - y2 * z1) + be * px + c0;
            out[3 * s + 1] = al * (y2 * z0 - y0 * z2) + be * py + c1;
            out[3 * s + 2] = al * (y0 * z1 - y1 * z0) + be * pz + c2;
        }
    }
}

extern "C" void kernel_launch(void* const* d_in, const int* in_sizes, int n_in,
                              void* d_out, int out_size)
{
    const float* t       = (const float*)d_in[0];
    const float* x       = (const float*)d_in[1];
    const float* R       = (const float*)d_in[2];
    const float* m       = (const float*)d_in[3];
    const float* Wl1     = (const float*)d_in[4];
    const float* Wd1     = (const float*)d_in[5];
    const float* Wl2     = (const float*)d_in[6];
    const float* Wd2     = (const float*)d_in[7];
    const float* Wl3     = (const float*)d_in[8];
    const float* Wd3     = (const float*)d_in[9];
    const float* Wl4     = (const float*)d_in[10];
    const float* Wd4     = (const float*)d_in[11];
    const float* Wb1_lin = (const float*)d_in[12];
    const float* Wb1_d1  = (const float*)d_in[13];
    const float* Wb1_d2  = (const float*)d_in[14];
    const float* Wb2_lin = (const float*)d_in[15];
    const float* Wb2_d1  = (const float*)d_in[16];
    const float* Wb2_d2  = (const float*)d_in[17];
    const float* Wout    = (const float*)d_in[18];
    float* out = (float*)d_out;

    const int nstates = in_sizes[1] / 3;
    const int nOct    = nstates / 8;

    const int threads = 256;
    const int blocks = (nOct + threads - 1) / threads > 0 ? (nOct + threads - 1) / threads : 1;

    fused_kernel<<<blocks, threads>>>(t, x, R, m,
                                      Wl1, Wd1, Wl2, Wd2, Wl3, Wd3, Wl4, Wd4,
                                      Wb1_lin, Wb1_d1, Wb1_d2,
                                      Wb2_lin, Wb2_d1, Wb2_d2,
                                      Wout, out, nOct, nstates);
}

// round 7
// speedup vs baseline: 1.1300x; 1.1300x over previous
#include <cuda_runtime.h>
#include <math.h>

// [0..8] M1, [9..17] M2, [18] alpha, [19] beta, [20..22] const vec c
__device__ float g_prep[24];

// ---------------------------------------------------------------------------
// Prep kernel: 256 threads stage ALL weights into shared memory in one
// parallel burst (independent loads -> one DRAM round trip), then warp 0
// computes the tiny batch-independent algebra from smem.
// ---------------------------------------------------------------------------
// Shared float offsets
#define SH_R      0      // 9
#define SH_M      9      // 60
#define SH_WL     69     // 4 x 60
#define SH_WD     309    // 4 x 9
#define SH_B1LIN  345    // 20
#define SH_B1D1   365    // 400
#define SH_B1D2   765    // 400
#define SH_B2LIN  1165   // 20
#define SH_B2D1   1185   // 400
#define SH_B2D2   1585   // 400
#define SH_WOUT   1985   // 20
#define SH_T      2005   // 1
#define SH_TOTAL  2006

__global__ void prep_kernel(const float* __restrict__ t,
                            const float* __restrict__ R,
                            const float* __restrict__ m,
                            const float* __restrict__ Wl1, const float* __restrict__ Wd1,
                            const float* __restrict__ Wl2, const float* __restrict__ Wd2,
                            const float* __restrict__ Wl3, const float* __restrict__ Wd3,
                            const float* __restrict__ Wl4, const float* __restrict__ Wd4,
                            const float* __restrict__ Wb1_lin,
                            const float* __restrict__ Wb1_d1, const float* __restrict__ Wb1_d2,
                            const float* __restrict__ Wb2_lin,
                            const float* __restrict__ Wb2_d1, const float* __restrict__ Wb2_d2,
                            const float* __restrict__ Wout)
{
    __shared__ float sh[SH_TOTAL];
    __shared__ float sM[4][9];
    const int tid = threadIdx.x;   // 256 threads

    // ---- Parallel staging: all loads independent, max MLP ----
    {
        // big arrays (400 each): 256 threads -> <=2 iters
        for (int j = tid; j < 400; j += 256) {
            sh[SH_B1D1 + j] = Wb1_d1[j];
            sh[SH_B1D2 + j] = Wb1_d2[j];
            sh[SH_B2D1 + j] = Wb2_d1[j];
            sh[SH_B2D2 + j] = Wb2_d2[j];
        }
        if (tid < 60) {
            sh[SH_M + tid] = m[tid];
            sh[SH_WL + 0 * 60 + tid] = Wl1[tid];
            sh[SH_WL + 1 * 60 + tid] = Wl2[tid];
            sh[SH_WL + 2 * 60 + tid] = Wl3[tid];
            sh[SH_WL + 3 * 60 + tid] = Wl4[tid];
        }
        if (tid < 9) {
            sh[SH_R + tid] = R[tid];
            sh[SH_WD + 0 * 9 + tid] = Wd1[tid];
            sh[SH_WD + 1 * 9 + tid] = Wd2[tid];
            sh[SH_WD + 2 * 9 + tid] = Wd3[tid];
            sh[SH_WD + 3 * 9 + tid] = Wd4[tid];
        }
        if (tid < 20) {
            sh[SH_B1LIN + tid] = Wb1_lin[tid];
            sh[SH_B2LIN + tid] = Wb2_lin[tid];
            sh[SH_WOUT + tid] = Wout[tid];
        }
        if (tid == 0) sh[SH_T] = t[0];
    }
    __syncthreads();
    if (tid >= 32) return;
    const int lane = tid;

    // mm[f][k] = (R@m)[k][f], stored into registers via smem scratch
    __shared__ float mm[20][3];
    for (int idx = lane; idx < 60; idx += 32) {
        int f = idx / 3, k = idx % 3;
        float s = 0.f;
        #pragma unroll
        for (int j = 0; j < 3; ++j) s += sh[SH_R + k * 3 + j] * sh[SH_M + j * 20 + f];
        mm[f][k] = s;
    }
    __syncwarp();

    if (lane < 4) {
        const float* Wl = &sh[SH_WL + lane * 60];
        const float* Wd = &sh[SH_WD + lane * 9];
        float y[3][3], d[3][3], o[3][3];
        #pragma unroll
        for (int oo = 0; oo < 3; ++oo)
            #pragma unroll
            for (int k = 0; k < 3; ++k) {
                float s = 0.f;
                #pragma unroll
                for (int f = 0; f < 20; ++f) s += Wl[oo * 20 + f] * mm[f][k];
                y[oo][k] = s;
            }
        #pragma unroll
        for (int oo = 0; oo < 3; ++oo)
            #pragma unroll
            for (int k = 0; k < 3; ++k) {
                float s = 0.f;
                #pragma unroll
                for (int f = 0; f < 3; ++f) s += Wd[oo * 3 + f] * y[f][k];
                d[oo][k] = s;
            }
        #pragma unroll
        for (int oo = 0; oo < 3; ++oo) {
            float kxd = -2.f * (y[oo][0] * d[oo][0] + y[oo][1] * d[oo][1] + y[oo][2] * d[oo][2]);
            float kdd = -2.f * (d[oo][0] * d[oo][0] + d[oo][1] * d[oo][1] + d[oo][2] * d[oo][2]);
            float denom = fminf(kdd, -1e-12f);
            float fac = (kxd < 0.f) ? 0.f : (kxd / denom);
            #pragma unroll
            for (int k = 0; k < 3; ++k) o[oo][k] = y[oo][k] - fac * d[oo][k];
        }
        #pragma unroll
        for (int p = 0; p < 3; ++p)
            #pragma unroll
            for (int q = 0; q < 3; ++q)
                sM[lane][p * 3 + q] =
                    o[0][p] * o[0][q] + o[1][p] * o[1][q] + o[2][p] * o[2][q];
    }
    __syncwarp();

    // Per-channel contractions from smem
    float pa = 0.f, pb = 0.f, pau = 0.f, pbu = 0.f;
    if (lane < 20) {
        float c1 = 0.f, c2 = 0.f, c1u = 0.f, c2u = 0.f;
        #pragma unroll
        for (int q = 0; q < 20; ++q) {
            float b1 = sh[SH_B1LIN + q], b2 = sh[SH_B2LIN + q];
            c1  += sh[SH_B1D1 + lane * 20 + q] * b1;
            c2  += sh[SH_B1D2 + lane * 20 + q] * b1;
            c1u += sh[SH_B2D1 + lane * 20 + q] * b2;
            c2u += sh[SH_B2D2 + lane * 20 + q] * b2;
        }
        float wo = sh[SH_WOUT + lane];
        pa  = wo * c1 * c2;
        pb  = wo * sh[SH_B1LIN + lane];
        pau = wo * c1u * c2u;
        pbu = wo * sh[SH_B2LIN + lane];
    }
    #pragma unroll
    for (int off = 16; off; off >>= 1) {
        pa  += __shfl_down_sync(0xffffffffu, pa, off);
        pb  += __shfl_down_sync(0xffffffffu, pb, off);
        pau += __shfl_down_sync(0xffffffffu, pau, off);
        pbu += __shfl_down_sync(0xffffffffu, pbu, off);
    }

    if (lane == 0) {
        float tv = sh[SH_T];
        float sv = sinf(tv), cv = cosf(tv);
        float u0[3] = {10.f * sv, 10.f * cv, 10.f * sv};
        float u[3];
        #pragma unroll
        for (int k = 0; k < 3; ++k)
            u[k] = sh[SH_R + k * 3 + 0] * u0[0] + sh[SH_R + k * 3 + 1] * u0[1]
                 + sh[SH_R + k * 3 + 2] * u0[2];
        float w1[3], w2[3];
        #pragma unroll
        for (int p = 0; p < 3; ++p) {
            w1[p] = sM[2][p * 3 + 0] * u[0] + sM[2][p * 3 + 1] * u[1] + sM[2][p * 3 + 2] * u[2];
            w2[p] = sM[3][p * 3 + 0] * u[0] + sM[3][p * 3 + 1] * u[1] + sM[3][p * 3 + 2] * u[2];
        }
        float cu[3] = {w1[1] * w2[2] - w1[2] * w2[1],
                       w1[2] * w2[0] - w1[0] * w2[2],
                       w1[0] * w2[1] - w1[1] * w2[0]};
        #pragma unroll
        for (int i = 0; i < 9; ++i) { g_prep[i] = sM[0][i]; g_prep[9 + i] = sM[1][i]; }
        g_prep[18] = pa;
        g_prep[19] = pb;
        #pragma unroll
        for (int k = 0; k < 3; ++k) g_prep[20 + k] = pau * cu[k] + pbu * u[k];
    }
}

// ---------------------------------------------------------------------------
// Main kernel: out_b = alpha * cross(M1 x_b, M2 x_b) + beta * x_b + c
// 8 states/thread: 6 front-batched float4 loads (MLP=6) + 6 float4 stores.
// Lean body: no prep code, low register class.
// ---------------------------------------------------------------------------
__global__ void main_kernel(const float* __restrict__ x, float* __restrict__ out, int nOct)
{
    int i = blockIdx.x * blockDim.x + threadIdx.x;
    if (i >= nOct) return;

    const float4* __restrict__ x4 = (const float4*)x;
    float4* __restrict__ o4 = (float4*)out;
    const long base = (long)i * 6;

    float4 v0 = x4[base + 0];
    float4 v1 = x4[base + 1];
    float4 v2 = x4[base + 2];
    float4 v3 = x4[base + 3];
    float4 v4 = x4[base + 4];
    float4 v5 = x4[base + 5];

    float M1[9], M2[9];
    #pragma unroll
    for (int j = 0; j < 9; ++j) { M1[j] = g_prep[j]; M2[j] = g_prep[9 + j]; }
    const float al = g_prep[18], be = g_prep[19];
    const float c0 = g_prep[20], c1 = g_prep[21], c2 = g_prep[22];

    float xs[24] = {v0.x, v0.y, v0.z, v0.w, v1.x, v1.y, v1.z, v1.w,
                    v2.x, v2.y, v2.z, v2.w, v3.x, v3.y, v3.z, v3.w,
                    v4.x, v4.y, v4.z, v4.w, v5.x, v5.y, v5.z, v5.w};
    float os[24];
    #pragma unroll
    for (int s = 0; s < 8; ++s) {
        float px = xs[3 * s + 0], py = xs[3 * s + 1], pz = xs[3 * s + 2];
        float y0 = M1[0] * px + M1[1] * py + M1[2] * pz;
        float y1 = M1[3] * px + M1[4] * py + M1[5] * pz;
        float y2 = M1[6] * px + M1[7] * py + M1[8] * pz;
        float z0 = M2[0] * px + M2[1] * py + M2[2] * pz;
        float z1 = M2[3] * px + M2[4] * py + M2[5] * pz;
        float z2 = M2[6] * px + M2[7] * py + M2[8] * pz;
        os[3 * s + 0] = al * (y1 * z2 - y2 * z1) + be * px + c0;
        os[3 * s + 1] = al * (y2 * z0 - y0 * z2) + be * py + c1;
        os[3 * s + 2] = al * (y0 * z1 - y1 * z0) + be * pz + c2;
    }

    o4[base + 0] = make_float4(os[0],  os[1],  os[2],  os[3]);
    o4[base + 1] = make_float4(os[4],  os[5],  os[6],  os[7]);
    o4[base + 2] = make_float4(os[8],  os[9],  os[10], os[11]);
    o4[base + 3] = make_float4(os[12], os[13], os[14], os[15]);
    o4[base + 4] = make_float4(os[16], os[17], os[18], os[19]);
    o4[base + 5] = make_float4(os[20], os[21], os[22], os[23]);
}

// Scalar tail (only launched when nstates % 8 != 0).
__global__ void tail_kernel(const float* __restrict__ x, float* __restrict__ out,
                            int start, int nstates)
{
    int s = start + blockIdx.x * blockDim.x + threadIdx.x;
    if (s >= nstates) return;
    float M1[9], M2[9];
    #pragma unroll
    for (int j = 0; j < 9; ++j) { M1[j] = g_prep[j]; M2[j] = g_prep[9 + j]; }
    const float al = g_prep[18], be = g_prep[19];
    float px = x[3 * s], py = x[3 * s + 1], pz = x[3 * s + 2];
    float y0 = M1[0] * px + M1[1] * py + M1[2] * pz;
    float y1 = M1[3] * px + M1[4] * py + M1[5] * pz;
    float y2 = M1[6] * px + M1[7] * py + M1[8] * pz;
    float z0 = M2[0] * px + M2[1] * py + M2[2] * pz;
    float z1 = M2[3] * px + M2[4] * py + M2[5] * pz;
    float z2 = M2[6] * px + M2[7] * py + M2[8] * pz;
    out[3 * s + 0] = al * (y1 * z2 - y2 * z1) + be * px + g_prep[20];
    out[3 * s + 1] = al * (y2 * z0 - y0 * z2) + be * py + g_prep[21];
    out[3 * s + 2] = al * (y0 * z1 - y1 * z0) + be * pz + g_prep[22];
}

extern "C" void kernel_launch(void* const* d_in, const int* in_sizes, int n_in,
                              void* d_out, int out_size)
{
    const float* t       = (const float*)d_in[0];
    const float* x       = (const float*)d_in[1];
    const float* R       = (const float*)d_in[2];
    const float* m       = (const float*)d_in[3];
    const float* Wl1     = (const float*)d_in[4];
    const float* Wd1     = (const float*)d_in[5];
    const float* Wl2     = (const float*)d_in[6];
    const float* Wd2     = (const float*)d_in[7];
    const float* Wl3     = (const float*)d_in[8];
    const float* Wd3     = (const float*)d_in[9];
    const float* Wl4     = (const float*)d_in[10];
    const float* Wd4     = (const float*)d_in[11];
    const float* Wb1_lin = (const float*)d_in[12];
    const float* Wb1_d1  = (const float*)d_in[13];
    const float* Wb1_d2  = (const float*)d_in[14];
    const float* Wb2_lin = (const float*)d_in[15];
    const float* Wb2_d1  = (const float*)d_in[16];
    const float* Wb2_d2  = (const float*)d_in[17];
    const float* Wout    = (const float*)d_in[18];
    float* out = (float*)d_out;

    const int nstates = in_sizes[1] / 3;
    const int nOct    = nstates / 8;
    const int tail    = nstates - nOct * 8;

    prep_kernel<<<1, 256>>>(t, R, m, Wl1, Wd1, Wl2, Wd2, Wl3, Wd3, Wl4, Wd4,
                            Wb1_lin, Wb1_d1, Wb1_d2, Wb2_lin, Wb2_d1, Wb2_d2, Wout);

    if (nOct > 0) {
        const int threads = 256;
        const int blocks = (nOct + threads - 1) / threads;
        main_kernel<<<blocks, threads>>>(x, out, nOct);
    }
    if (tail > 0) {
        tail_kernel<<<1, 32>>>(x, out, nOct * 8, nstates);
    }
}

// round 9
// speedup vs baseline: 1.3359x; 1.1823x over previous
#include <cuda_runtime.h>
#include <math.h>

// [0..8] M1, [9..17] M2, [18] alpha, [19] beta, [20..22] const vec c
__device__ float g_prep[24];

// ---------------------------------------------------------------------------
// Prep kernel: 256 threads stage ALL weights into shared memory in one
// parallel burst, then warp 0 computes the tiny batch-independent algebra.
// ---------------------------------------------------------------------------
#define SH_R      0      // 9
#define SH_M      9      // 60
#define SH_WL     69     // 4 x 60
#define SH_WD     309    // 4 x 9
#define SH_B1LIN  345    // 20
#define SH_B1D1   365    // 400
#define SH_B1D2   765    // 400
#define SH_B2LIN  1165   // 20
#define SH_B2D1   1185   // 400
#define SH_B2D2   1585   // 400
#define SH_WOUT   1985   // 20
#define SH_T      2005   // 1
#define SH_TOTAL  2006

__global__ void prep_kernel(const float* __restrict__ t,
                            const float* __restrict__ R,
                            const float* __restrict__ m,
                            const float* __restrict__ Wl1, const float* __restrict__ Wd1,
                            const float* __restrict__ Wl2, const float* __restrict__ Wd2,
                            const float* __restrict__ Wl3, const float* __restrict__ Wd3,
                            const float* __restrict__ Wl4, const float* __restrict__ Wd4,
                            const float* __restrict__ Wb1_lin,
                            const float* __restrict__ Wb1_d1, const float* __restrict__ Wb1_d2,
                            const float* __restrict__ Wb2_lin,
                            const float* __restrict__ Wb2_d1, const float* __restrict__ Wb2_d2,
                            const float* __restrict__ Wout)
{
    __shared__ float sh[SH_TOTAL];
    __shared__ float sM[4][9];
    const int tid = threadIdx.x;   // 256 threads

    // ---- Parallel staging: all loads independent, max MLP ----
    {
        for (int j = tid; j < 400; j += 256) {
            sh[SH_B1D1 + j] = Wb1_d1[j];
            sh[SH_B1D2 + j] = Wb1_d2[j];
            sh[SH_B2D1 + j] = Wb2_d1[j];
            sh[SH_B2D2 + j] = Wb2_d2[j];
        }
        if (tid < 60) {
            sh[SH_M + tid] = m[tid];
            sh[SH_WL + 0 * 60 + tid] = Wl1[tid];
            sh[SH_WL + 1 * 60 + tid] = Wl2[tid];
            sh[SH_WL + 2 * 60 + tid] = Wl3[tid];
            sh[SH_WL + 3 * 60 + tid] = Wl4[tid];
        }
        if (tid < 9) {
            sh[SH_R + tid] = R[tid];
            sh[SH_WD + 0 * 9 + tid] = Wd1[tid];
            sh[SH_WD + 1 * 9 + tid] = Wd2[tid];
            sh[SH_WD + 2 * 9 + tid] = Wd3[tid];
            sh[SH_WD + 3 * 9 + tid] = Wd4[tid];
        }
        if (tid < 20) {
            sh[SH_B1LIN + tid] = Wb1_lin[tid];
            sh[SH_B2LIN + tid] = Wb2_lin[tid];
            sh[SH_WOUT + tid] = Wout[tid];
        }
        if (tid == 0) sh[SH_T] = t[0];
    }
    __syncthreads();
    if (tid >= 32) return;
    const int lane = tid;

    __shared__ float mm[20][3];
    for (int idx = lane; idx < 60; idx += 32) {
        int f = idx / 3, k = idx % 3;
        float s = 0.f;
        #pragma unroll
        for (int j = 0; j < 3; ++j) s += sh[SH_R + k * 3 + j] * sh[SH_M + j * 20 + f];
        mm[f][k] = s;
    }
    __syncwarp();

    if (lane < 4) {
        const float* Wl = &sh[SH_WL + lane * 60];
        const float* Wd = &sh[SH_WD + lane * 9];
        float y[3][3], d[3][3], o[3][3];
        #pragma unroll
        for (int oo = 0; oo < 3; ++oo)
            #pragma unroll
            for (int k = 0; k < 3; ++k) {
                float s = 0.f;
                #pragma unroll
                for (int f = 0; f < 20; ++f) s += Wl[oo * 20 + f] * mm[f][k];
                y[oo][k] = s;
            }
        #pragma unroll
        for (int oo = 0; oo < 3; ++oo)
            #pragma unroll
            for (int k = 0; k < 3; ++k) {
                float s = 0.f;
                #pragma unroll
                for (int f = 0; f < 3; ++f) s += Wd[oo * 3 + f] * y[f][k];
                d[oo][k] = s;
            }
        #pragma unroll
        for (int oo = 0; oo < 3; ++oo) {
            float kxd = -2.f * (y[oo][0] * d[oo][0] + y[oo][1] * d[oo][1] + y[oo][2] * d[oo][2]);
            float kdd = -2.f * (d[oo][0] * d[oo][0] + d[oo][1] * d[oo][1] + d[oo][2] * d[oo][2]);
            float denom = fminf(kdd, -1e-12f);
            float fac = (kxd < 0.f) ? 0.f : (kxd / denom);
            #pragma unroll
            for (int k = 0; k < 3; ++k) o[oo][k] = y[oo][k] - fac * d[oo][k];
        }
        #pragma unroll
        for (int p = 0; p < 3; ++p)
            #pragma unroll
            for (int q = 0; q < 3; ++q)
                sM[lane][p * 3 + q] =
                    o[0][p] * o[0][q] + o[1][p] * o[1][q] + o[2][p] * o[2][q];
    }
    __syncwarp();

    float pa = 0.f, pb = 0.f, pau = 0.f, pbu = 0.f;
    if (lane < 20) {
        float c1 = 0.f, c2 = 0.f, c1u = 0.f, c2u = 0.f;
        #pragma unroll
        for (int q = 0; q < 20; ++q) {
            float b1 = sh[SH_B1LIN + q], b2 = sh[SH_B2LIN + q];
            c1  += sh[SH_B1D1 + lane * 20 + q] * b1;
            c2  += sh[SH_B1D2 + lane * 20 + q] * b1;
            c1u += sh[SH_B2D1 + lane * 20 + q] * b2;
            c2u += sh[SH_B2D2 + lane * 20 + q] * b2;
        }
        float wo = sh[SH_WOUT + lane];
        pa  = wo * c1 * c2;
        pb  = wo * sh[SH_B1LIN + lane];
        pau = wo * c1u * c2u;
        pbu = wo * sh[SH_B2LIN + lane];
    }
    #pragma unroll
    for (int off = 16; off; off >>= 1) {
        pa  += __shfl_down_sync(0xffffffffu, pa, off);
        pb  += __shfl_down_sync(0xffffffffu, pb, off);
        pau += __shfl_down_sync(0xffffffffu, pau, off);
        pbu += __shfl_down_sync(0xffffffffu, pbu, off);
    }

    if (lane == 0) {
        float tv = sh[SH_T];
        float sv = sinf(tv), cv = cosf(tv);
        float u0[3] = {10.f * sv, 10.f * cv, 10.f * sv};
        float u[3];
        #pragma unroll
        for (int k = 0; k < 3; ++k)
            u[k] = sh[SH_R + k * 3 + 0] * u0[0] + sh[SH_R + k * 3 + 1] * u0[1]
                 + sh[SH_R + k * 3 + 2] * u0[2];
        float w1[3], w2[3];
        #pragma unroll
        for (int p = 0; p < 3; ++p) {
            w1[p] = sM[2][p * 3 + 0] * u[0] + sM[2][p * 3 + 1] * u[1] + sM[2][p * 3 + 2] * u[2];
            w2[p] = sM[3][p * 3 + 0] * u[0] + sM[3][p * 3 + 1] * u[1] + sM[3][p * 3 + 2] * u[2];
        }
        float cu[3] = {w1[1] * w2[2] - w1[2] * w2[1],
                       w1[2] * w2[0] - w1[0] * w2[2],
                       w1[0] * w2[1] - w1[1] * w2[0]};
        #pragma unroll
        for (int i = 0; i < 9; ++i) { g_prep[i] = sM[0][i]; g_prep[9 + i] = sM[1][i]; }
        g_prep[18] = pa;
        g_prep[19] = pb;
        #pragma unroll
        for (int k = 0; k < 3; ++k) g_prep[20 + k] = pau * cu[k] + pbu * u[k];
    }
}

// ---------------------------------------------------------------------------
// Main kernel: out_b = alpha * cross(M1 x_b, M2 x_b) + beta * x_b + c
// 4 states/thread (3 float4 in / 3 float4 out), launch_bounds to push
// occupancy to 6 blocks/SM (48 warps).
// ---------------------------------------------------------------------------
__global__ void __launch_bounds__(256, 6)
main_kernel(const float* __restrict__ x, float* __restrict__ out, int nquad)
{
    int i = blockIdx.x * blockDim.x + threadIdx.x;
    if (i >= nquad) return;

    const float4* __restrict__ x4 = (const float4*)x;
    float4* __restrict__ o4 = (float4*)out;

    float4 a = x4[3 * i + 0];
    float4 b = x4[3 * i + 1];
    float4 c = x4[3 * i + 2];

    float M1[9], M2[9];
    #pragma unroll
    for (int j = 0; j < 9; ++j) { M1[j] = g_prep[j]; M2[j] = g_prep[9 + j]; }
    const float al = g_prep[18], be = g_prep[19];
    const float c0 = g_prep[20], c1 = g_prep[21], c2 = g_prep[22];

    float xs[12] = {a.x, a.y, a.z, a.w, b.x, b.y, b.z, b.w, c.x, c.y, c.z, c.w};
    float os[12];

    #pragma unroll
    for (int s = 0; s < 4; ++s) {
        float px = xs[3 * s + 0], py = xs[3 * s + 1], pz = xs[3 * s + 2];
        float y0 = M1[0] * px + M1[1] * py + M1[2] * pz;
        float y1 = M1[3] * px + M1[4] * py + M1[5] * pz;
        float y2 = M1[6] * px + M1[7] * py + M1[8] * pz;
        float z0 = M2[0] * px + M2[1] * py + M2[2] * pz;
        float z1 = M2[3] * px + M2[4] * py + M2[5] * pz;
        float z2 = M2[6] * px + M2[7] * py + M2[8] * pz;
        os[3 * s + 0] = al * (y1 * z2 - y2 * z1) + be * px + c0;
        os[3 * s + 1] = al * (y2 * z0 - y0 * z2) + be * py + c1;
        os[3 * s + 2] = al * (y0 * z1 - y1 * z0) + be * pz + c2;
    }

    o4[3 * i + 0] = make_float4(os[0], os[1], os[2],  os[3]);
    o4[3 * i + 1] = make_float4(os[4], os[5], os[6],  os[7]);
    o4[3 * i + 2] = make_float4(os[8], os[9], os[10], os[11]);
}

// Scalar tail (only launched when nstates % 4 != 0).
__global__ void tail_kernel(const float* __restrict__ x, float* __restrict__ out,
                            int start, int nstates)
{
    int s = start + blockIdx.x * blockDim.x + threadIdx.x;
    if (s >= nstates) return;
    float M1[9], M2[9];
    #pragma unroll
    for (int j = 0; j < 9; ++j) { M1[j] = g_prep[j]; M2[j] = g_prep[9 + j]; }
    const float al = g_prep[18], be = g_prep[19];
    float px = x[3 * s], py = x[3 * s + 1], pz = x[3 * s + 2];
    float y0 = M1[0] * px + M1[1] * py + M1[2] * pz;
    float y1 = M1[3] * px + M1[4] * py + M1[5] * pz;
    float y2 = M1[6] * px + M1[7] * py + M1[8] * pz;
    float z0 = M2[0] * px + M2[1] * py + M2[2] * pz;
    float z1 = M2[3] * px + M2[4] * py + M2[5] * pz;
    float z2 = M2[6] * px + M2[7] * py + M2[8] * pz;
    out[3 * s + 0] = al * (y1 * z2 - y2 * z1) + be * px + g_prep[20];
    out[3 * s + 1] = al * (y2 * z0 - y0 * z2) + be * py + g_prep[21];
    out[3 * s + 2] = al * (y0 * z1 - y1 * z0) + be * pz + g_prep[22];
}

extern "C" void kernel_launch(void* const* d_in, const int* in_sizes, int n_in,
                              void* d_out, int out_size)
{
    const float* t       = (const float*)d_in[0];
    const float* x       = (const float*)d_in[1];
    const float* R       = (const float*)d_in[2];
    const float* m       = (const float*)d_in[3];
    const float* Wl1     = (const float*)d_in[4];
    const float* Wd1     = (const float*)d_in[5];
    const float* Wl2     = (const float*)d_in[6];
    const float* Wd2     = (const float*)d_in[7];
    const float* Wl3     = (const float*)d_in[8];
    const float* Wd3     = (const float*)d_in[9];
    const float* Wl4     = (const float*)d_in[10];
    const float* Wd4     = (const float*)d_in[11];
    const float* Wb1_lin = (const float*)d_in[12];
    const float* Wb1_d1  = (const float*)d_in[13];
    const float* Wb1_d2  = (const float*)d_in[14];
    const float* Wb2_lin = (const float*)d_in[15];
    const float* Wb2_d1  = (const float*)d_in[16];
    const float* Wb2_d2  = (const float*)d_in[17];
    const float* Wout    = (const float*)d_in[18];
    float* out = (float*)d_out;

    const int nstates = in_sizes[1] / 3;
    const int nquad   = nstates / 4;
    const int tail    = nstates - nquad * 4;

    prep_kernel<<<1, 256>>>(t, R, m, Wl1, Wd1, Wl2, Wd2, Wl3, Wd3, Wl4, Wd4,
                            Wb1_lin, Wb1_d1, Wb1_d2, Wb2_lin, Wb2_d1, Wb2_d2, Wout);

    if (nquad > 0) {
        const int threads = 256;
        const int blocks = (nquad + threads - 1) / threads;
        main_kernel<<<blocks, threads>>>(x, out, nquad);
    }
    if (tail > 0) {
        tail_kernel<<<1, 32>>>(x, out, nquad * 4, nstates);
    }
}